// round 16
// baseline (speedup 1.0000x reference)
#include <cuda_runtime.h>
#include <stdint.h>
#include <math.h>

typedef unsigned long long ull;

// Problem constants
#define B_   64
#define T_   64
#define N_   32
#define D_   32
#define H_   128
#define E_   256
#define G4_  512   // 4*H
#define F0_  160   // D+H
#define F1_  256   // 2*H
#define NTH  256
#define NCOL 64    // h-columns owned per CTA (per gate), cluster of 2

// Shared memory layout (float offsets)
#define FS   33    // feature-major row stride (odd -> conflict-free column reads)
#define AS   68    // aggT dup-pair row stride (68*4=272 B, 16B-aligned rows)

#define SMO_H0   0                          // [2][128*FS] double buffered
#define SMO_H1   (SMO_H0 + 2*H_*FS)         // 8448
#define SMO_C0   (SMO_H1 + 2*H_*FS)         // 16896  [32][NCOL] local cols
#define SMO_C1   (SMO_C0 + N_*NCOL)         // 18944
#define SMO_AGG  (SMO_C1 + N_*NCOL)         // 20992  [256][AS] dup-pair layout
#define SMO_X    (SMO_AGG + F1_*AS)         // 38400  [32][FS]
#define SMO_AN   (SMO_X + D_*FS)            // 39456  [m][n] 32x32
#define SMO_DINV (SMO_AN + N_*N_)           // 40480
#define SM_FLOATS (SMO_DINV + 32)           // 40512
#define SM_BYTES (SM_FLOATS * 4)            // 162048 B

// Output buffer offsets: (output, zlat, mu, logvar, output_logvar)
#define OFF_OUT 0
#define OFF_Z   (B_*T_*N_*D_)
#define OFF_MU  (OFF_Z  + B_*N_*H_)
#define OFF_LV  (OFF_MU + B_*N_*H_)
#define OFF_OLV (OFF_LV + B_*N_*H_)

// ---------------- packed f32x2 helpers ----------------
__device__ __forceinline__ ull pk2(float lo, float hi) {
    ull r;
    asm("mov.b64 %0, {%1, %2};" : "=l"(r) : "f"(lo), "f"(hi));
    return r;
}
__device__ __forceinline__ void upk2(ull v, float& lo, float& hi) {
    asm("mov.b64 {%0, %1}, %2;" : "=f"(lo), "=f"(hi) : "l"(v));
}
__device__ __forceinline__ ull ffma2(ull a, ull b, ull c) {
    ull d;
    asm("fma.rn.f32x2 %0, %1, %2, %3;" : "=l"(d) : "l"(a), "l"(b), "l"(c));
    return d;
}

// ---------------- cluster helpers ----------------
__device__ __forceinline__ uint32_t smem_u32(const void* p) {
    uint32_t a;
    asm("{ .reg .u64 t; cvta.to.shared.u64 t, %1; cvt.u32.u64 %0, t; }"
        : "=r"(a) : "l"(p));
    return a;
}
__device__ __forceinline__ uint32_t map_peer(uint32_t laddr, uint32_t peer_rank) {
    uint32_t r;
    asm("mapa.shared::cluster.u32 %0, %1, %2;" : "=r"(r) : "r"(laddr), "r"(peer_rank));
    return r;
}
__device__ __forceinline__ void stc_f32(uint32_t addr, float v) {
    asm volatile("st.shared::cluster.f32 [%0], %1;" :: "r"(addr), "f"(v) : "memory");
}
#define CSYNC() do { \
    asm volatile("barrier.cluster.arrive.aligned;" ::: "memory"); \
    asm volatile("barrier.cluster.wait.aligned;"   ::: "memory"); \
} while (0)

// ---------------- activations (accurate: exp-based) ----------------
__device__ __forceinline__ float sigf(float x) {
    return __fdividef(1.0f, 1.0f + __expf(-x));
}
__device__ __forceinline__ float tanhg(float x) {
    return __fdividef(2.0f, 1.0f + __expf(-2.0f * x)) - 1.0f;
}

// ---------------- GCN aggregation (full, duplicated per CTA) ----------------
// aggT[f][2n]=aggT[f][2n+1]= sum_m An[n][m]*src[f][m]; An stored transposed [m][n].
template<int F, int R0>
__device__ __forceinline__ void agg_f(float* __restrict__ aggT,
                                      const float* __restrict__ An,
                                      const float* __restrict__ s0,
                                      const float* __restrict__ s1,
                                      int tid) {
    if (tid < F) {
        const float* src = (tid < R0) ? (s0 + tid * FS) : (s1 + (tid - R0) * FS);
        ull acc[16];
        #pragma unroll
        for (int p = 0; p < 16; p++) acc[p] = 0ULL;
        #pragma unroll 4
        for (int m = 0; m < 32; m++) {
            const float xv = src[m];
            const ull xd = pk2(xv, xv);
            const ulonglong2* Am = (const ulonglong2*)(An + m * 32);  // broadcast
            #pragma unroll
            for (int q = 0; q < 8; q++) {
                const ulonglong2 w = Am[q];
                acc[2*q]   = ffma2(xd, w.x, acc[2*q]);
                acc[2*q+1] = ffma2(xd, w.y, acc[2*q+1]);
            }
        }
        float* dst = aggT + tid * AS;
        #pragma unroll
        for (int p = 0; p < 16; p++) {
            float a, b2;
            upk2(acc[p], a, b2);
            *(float4*)(dst + 4*p) = make_float4(a, a, b2, b2);  // dup-pair store
        }
    }
}

// ---------------- LSTM cell half: GEMM (cols [rank*64, rank*64+64)) + gates ----
template<int K>
__device__ __forceinline__ void gemm_gates(const float* __restrict__ W,
                                           const float* __restrict__ bias,
                                           const float* __restrict__ aggT,
                                           float* __restrict__ hT,
                                           uint32_t hT_peer,
                                           float* __restrict__ cB,
                                           int rank, int tid) {
    const int rg = tid >> 5;
    const int cg = tid & 31;
    const int n0 = rg * 4;
    const int jl = cg * 2;             // local col pair within 64
    const int jg = rank * NCOL + jl;   // global col within gate block H

    ull acc[4][4];                     // [row r][gate g], u64 = 2 cols
    #pragma unroll
    for (int g = 0; g < 4; g++) {
        const ull bv = *(const ull*)(bias + g * H_ + jg);
        acc[0][g] = bv; acc[1][g] = bv; acc[2][g] = bv; acc[3][g] = bv;
    }

    const float* ap = aggT + n0 * 2;   // dup-pair layout: LDS gives (a,a) directly
    const float* wp = W + jg;
    #pragma unroll 4
    for (int k = 0; k < K; k++) {
        const ulonglong2 a01 = *(const ulonglong2*)ap;        // (a0,a0),(a1,a1)
        const ulonglong2 a23 = *(const ulonglong2*)(ap + 4);  // (a2,a2),(a3,a3)
        ap += AS;
        #pragma unroll
        for (int g = 0; g < 4; g++) {
            const ull w = __ldg((const ull*)(wp + g * H_));    // packed (wj, wj+1)
            acc[0][g] = ffma2(a01.x, w, acc[0][g]);
            acc[1][g] = ffma2(a01.y, w, acc[1][g]);
            acc[2][g] = ffma2(a23.x, w, acc[2][g]);
            acc[3][g] = ffma2(a23.y, w, acc[3][g]);
        }
        wp += G4_;
    }

    #pragma unroll
    for (int r = 0; r < 4; r++) {
        const int n = n0 + r;
        float i0, i1, f0, f1, g0, g1, o0, o1;
        upk2(acc[r][0], i0, i1);
        upk2(acc[r][1], f0, f1);
        upk2(acc[r][2], g0, g1);
        upk2(acc[r][3], o0, o1);
        float2 c = *(float2*)(cB + n * NCOL + jl);
        const float cn0 = sigf(f0) * c.x + sigf(i0) * tanhg(g0);
        const float cn1 = sigf(f1) * c.y + sigf(i1) * tanhg(g1);
        *(float2*)(cB + n * NCOL + jl) = make_float2(cn0, cn1);
        const float hv0 = sigf(o0) * tanhg(cn0);
        const float hv1 = sigf(o1) * tanhg(cn1);
        const int o0i = jg * FS + n;
        const int o1i = o0i + FS;
        hT[o0i] = hv0;
        hT[o1i] = hv1;
        stc_f32(hT_peer + o0i * 4, hv0);   // exchange h chunk to peer CTA
        stc_f32(hT_peer + o1i * 4, hv1);
    }
}

// ---------------- latent head (runs once; split cols by rank) ----------------
__device__ __forceinline__ void pnl_H(const float* __restrict__ h1T,
                                      const float* __restrict__ Wmu, const float* __restrict__ bmu,
                                      const float* __restrict__ Wlv, const float* __restrict__ blv,
                                      const float* __restrict__ eps_g,
                                      float* __restrict__ gmu, float* __restrict__ glv,
                                      float* __restrict__ gz,
                                      float* __restrict__ zbuf, uint32_t zbuf_peer,
                                      int b, int rank, int tid) {
    const int n  = tid >> 3;
    const int j0 = rank * NCOL + (tid & 7) * 8;
    float am[8] = {0,0,0,0,0,0,0,0};
    float al[8] = {0,0,0,0,0,0,0,0};
    const float* wm = Wmu + n * (H_ * H_) + j0;
    const float* wl = Wlv + n * (H_ * H_) + j0;
    const float* hp = h1T + n;
    for (int h = 0; h < H_; h++) {
        const float a = hp[h * FS];
        const float4 u0 = __ldg((const float4*)wm);
        const float4 u1 = __ldg((const float4*)(wm + 4));
        const float4 v0 = __ldg((const float4*)wl);
        const float4 v1 = __ldg((const float4*)(wl + 4));
        am[0] = fmaf(a, u0.x, am[0]); am[1] = fmaf(a, u0.y, am[1]);
        am[2] = fmaf(a, u0.z, am[2]); am[3] = fmaf(a, u0.w, am[3]);
        am[4] = fmaf(a, u1.x, am[4]); am[5] = fmaf(a, u1.y, am[5]);
        am[6] = fmaf(a, u1.z, am[6]); am[7] = fmaf(a, u1.w, am[7]);
        al[0] = fmaf(a, v0.x, al[0]); al[1] = fmaf(a, v0.y, al[1]);
        al[2] = fmaf(a, v0.z, al[2]); al[3] = fmaf(a, v0.w, al[3]);
        al[4] = fmaf(a, v1.x, al[4]); al[5] = fmaf(a, v1.y, al[5]);
        al[6] = fmaf(a, v1.z, al[6]); al[7] = fmaf(a, v1.w, al[7]);
        wm += H_; wl += H_;
    }
    const int gbase = b * (N_ * H_) + n * H_ + j0;
    const int bbase = n * H_ + j0;
    #pragma unroll
    for (int c = 0; c < 8; c++) {
        const float m = am[c] + bmu[bbase + c];
        const float l = al[c] + blv[bbase + c];
        const float z = m + eps_g[gbase + c] * __expf(l);
        gmu[gbase + c] = m;
        glv[gbase + c] = l;
        gz[gbase + c]  = z;
        const int zi = (j0 + c) * AS + n;   // feature-major staged z (stride AS)
        zbuf[zi] = z;
        stc_f32(zbuf_peer + zi * 4, z);
    }
}

// ---------------- output head (split d-cols by rank; also feeds back xT) ------
__device__ __forceinline__ void pnl_D(const float* __restrict__ srcT, int sstride,
                                      const float* __restrict__ Who, const float* __restrict__ bho,
                                      const float* __restrict__ Wholv, const float* __restrict__ bholv,
                                      float* __restrict__ gout, float* __restrict__ goutlv,
                                      float* __restrict__ xT, uint32_t xT_peer,
                                      int b, int tt, int rank, int tid) {
    const int n  = tid >> 3;
    const int d0 = rank * 16 + (tid & 7) * 2;
    ull ao = 0ULL, av = 0ULL;
    const float* w1 = Who   + n * (H_ * D_) + d0;
    const float* w2 = Wholv + n * (H_ * D_) + d0;
    const float* sp = srcT + n;
    #pragma unroll 4
    for (int h = 0; h < H_; h++) {
        const float a = sp[h * sstride];
        const ull ad = pk2(a, a);
        ao = ffma2(ad, __ldg((const ull*)w1), ao);
        av = ffma2(ad, __ldg((const ull*)w2), av);
        w1 += D_; w2 += D_;
    }
    float o0, o1, q0, q1;
    upk2(ao, o0, o1);
    upk2(av, q0, q1);
    const int bb = n * D_ + d0;
    o0 += bho[bb];   o1 += bho[bb + 1];
    q0 += bholv[bb]; q1 += bholv[bb + 1];
    const int goff = (b * T_ + tt) * (N_ * D_) + n * D_ + d0;
    *(float2*)(gout + goff)   = make_float2(o0, o1);
    *(float2*)(goutlv + goff) = make_float2(q0, q1);
    const int x0 = d0 * FS + n;
    xT[x0]      = o0;
    xT[x0 + FS] = o1;
    stc_f32(xT_peer + x0 * 4,        o0);
    stc_f32(xT_peer + (x0 + FS) * 4, o1);
}

// ---------------- main: cluster of 2 CTAs per batch element ----------------
__global__ void __launch_bounds__(NTH, 1) __cluster_dims__(2, 1, 1)
glstm_kernel(const float* __restrict__ ts, const int* __restrict__ ei,
             const float* __restrict__ Wen0, const float* __restrict__ ben0,
             const float* __restrict__ Wen1, const float* __restrict__ ben1,
             const float* __restrict__ Wde0, const float* __restrict__ bde0,
             const float* __restrict__ Wde1, const float* __restrict__ bde1,
             const float* __restrict__ Wmu, const float* __restrict__ bmu,
             const float* __restrict__ Wlv, const float* __restrict__ blv,
             const float* __restrict__ Who, const float* __restrict__ bho,
             const float* __restrict__ Wholv, const float* __restrict__ bholv,
             const float* __restrict__ eps, float* __restrict__ out) {
    extern __shared__ float sm[];
    const int tid = threadIdx.x;
    const int b   = blockIdx.x >> 1;
    uint32_t rank;
    asm("mov.u32 %0, %%cluster_ctarank;" : "=r"(rank));
    const uint32_t lbase = smem_u32(sm);
    const uint32_t pbase = map_peer(lbase, rank ^ 1u);

    float* h0buf = sm + SMO_H0;
    float* h1buf = sm + SMO_H1;
    float* c0B   = sm + SMO_C0;
    float* c1B   = sm + SMO_C1;
    float* aggT  = sm + SMO_AGG;
    float* xT    = sm + SMO_X;
    float* An    = sm + SMO_AN;
    float* dinv  = sm + SMO_DINV;

    float* gout   = out + OFF_OUT;
    float* gz     = out + OFF_Z;
    float* gmu    = out + OFF_MU;
    float* glv    = out + OFF_LV;
    float* goutlv = out + OFF_OLV;

    // ---- init: zero state, build normalized adjacency (duplicated per CTA) ----
    for (int i = tid; i < SMO_AGG; i += NTH) sm[i] = 0.0f;   // h0/h1 (both bufs), c0, c1
    float* C = aggT;                                          // scratch counts [n][m]
    for (int i = tid; i < N_ * N_; i += NTH) C[i] = 0.0f;
    __syncthreads();
    if (tid < E_) atomicAdd(&C[ei[E_ + tid] * N_ + ei[tid]], 1.0f);
    __syncthreads();
    if (tid < N_) {
        C[tid * N_ + tid] += 1.0f;
        float s = 0.0f;
        for (int m = 0; m < N_; m++) s += C[tid * N_ + m];
        dinv[tid] = 1.0f / sqrtf(s);
    }
    __syncthreads();
    for (int i = tid; i < N_ * N_; i += NTH) {
        const int n = i >> 5, m = i & 31;
        An[m * N_ + n] = dinv[n] * C[i] * dinv[m];            // store transposed [m][n]
    }
    CSYNC();   // peer init complete before any remote h writes

    // ---- encoder (steps 0..T-1) ----
    for (int s = 0; s < T_; s++) {
        const int p = s & 1;
        float* h0c = h0buf + p * (H_ * FS);
        float* h0p = h0buf + (p ^ 1) * (H_ * FS);
        float* h1c = h1buf + p * (H_ * FS);
        float* h1p = h1buf + (p ^ 1) * (H_ * FS);
        {   // stage x_t feature-major (full, per CTA)
            const int n = tid >> 3, d0 = (tid & 7) * 4;
            const float4 v = *(const float4*)(ts + ((b * T_ + s) * N_ + n) * D_ + d0);
            xT[(d0 + 0) * FS + n] = v.x;
            xT[(d0 + 1) * FS + n] = v.y;
            xT[(d0 + 2) * FS + n] = v.z;
            xT[(d0 + 3) * FS + n] = v.w;
        }
        __syncthreads();
        agg_f<F0_, D_>(aggT, An, xT, h0p, tid);
        __syncthreads();
        gemm_gates<F0_>(Wen0, ben0, aggT, h0c,
                        pbase + (uint32_t)(SMO_H0 + p * H_ * FS) * 4, c0B, rank, tid);
        CSYNC();
        agg_f<F1_, H_>(aggT, An, h0c, h1p, tid);
        __syncthreads();
        gemm_gates<F1_>(Wen1, ben1, aggT, h1c,
                        pbase + (uint32_t)(SMO_H1 + p * H_ * FS) * 4, c1B, rank, tid);
        CSYNC();
    }

    // ---- latent head ----
    float* h1f = h1buf + ((T_ - 1) & 1) * (H_ * FS);
    pnl_H(h1f, Wmu, bmu, Wlv, blv, eps, gmu, glv, gz,
          aggT, pbase + (uint32_t)SMO_AGG * 4, b, (int)rank, tid);
    CSYNC();
    pnl_D(aggT, AS, Who, bho, Wholv, bholv, gout, goutlv,
          xT, pbase + (uint32_t)SMO_X * 4, b, T_ - 1, (int)rank, tid);
    CSYNC();

    // ---- decoder (steps T..2T-2 -> timesteps T-2..0) ----
    for (int s = T_; s < 2 * T_ - 1; s++) {
        const int p = s & 1;
        float* h0c = h0buf + p * (H_ * FS);
        float* h0p = h0buf + (p ^ 1) * (H_ * FS);
        float* h1c = h1buf + p * (H_ * FS);
        float* h1p = h1buf + (p ^ 1) * (H_ * FS);
        agg_f<F0_, D_>(aggT, An, xT, h0p, tid);
        __syncthreads();
        gemm_gates<F0_>(Wde0, bde0, aggT, h0c,
                        pbase + (uint32_t)(SMO_H0 + p * H_ * FS) * 4, c0B, rank, tid);
        CSYNC();
        agg_f<F1_, H_>(aggT, An, h0c, h1p, tid);
        __syncthreads();
        gemm_gates<F1_>(Wde1, bde1, aggT, h1c,
                        pbase + (uint32_t)(SMO_H1 + p * H_ * FS) * 4, c1B, rank, tid);
        CSYNC();
        pnl_D(h1c, FS, Who, bho, Wholv, bholv, gout, goutlv,
              xT, pbase + (uint32_t)SMO_X * 4, b, T_ - 2 - (s - T_), (int)rank, tid);
        CSYNC();
    }
}

extern "C" void kernel_launch(void* const* d_in, const int* in_sizes, int n_in,
                              void* d_out, int out_size) {
    (void)in_sizes; (void)n_in; (void)out_size;
    const float* ts    = (const float*)d_in[0];
    const int*   ei    = (const int*)  d_in[1];
    const float* Wen0  = (const float*)d_in[2];
    const float* ben0  = (const float*)d_in[3];
    const float* Wen1  = (const float*)d_in[4];
    const float* ben1  = (const float*)d_in[5];
    const float* Wde0  = (const float*)d_in[6];
    const float* bde0  = (const float*)d_in[7];
    const float* Wde1  = (const float*)d_in[8];
    const float* bde1  = (const float*)d_in[9];
    const float* Wmu   = (const float*)d_in[10];
    const float* bmu   = (const float*)d_in[11];
    const float* Wlv   = (const float*)d_in[12];
    const float* blv   = (const float*)d_in[13];
    const float* Who   = (const float*)d_in[14];
    const float* bho   = (const float*)d_in[15];
    const float* Wholv = (const float*)d_in[16];
    const float* bholv = (const float*)d_in[17];
    const float* eps   = (const float*)d_in[18];
    float* o = (float*)d_out;

    cudaFuncSetAttribute(glstm_kernel, cudaFuncAttributeMaxDynamicSharedMemorySize, SM_BYTES);
    glstm_kernel<<<B_ * 2, NTH, SM_BYTES>>>(ts, ei, Wen0, ben0, Wen1, ben1,
                                            Wde0, bde0, Wde1, bde1,
                                            Wmu, bmu, Wlv, blv,
                                            Who, bho, Wholv, bholv, eps, o);
}

// round 17
// speedup vs baseline: 1.1780x; 1.1780x over previous
#include <cuda_runtime.h>
#include <stdint.h>
#include <math.h>

typedef unsigned long long ull;

// Problem constants
#define B_   64
#define T_   64
#define N_   32
#define D_   32
#define H_   128
#define E_   256
#define G4_  512   // 4*H
#define F0_  160   // D+H
#define F1_  256   // 2*H
#define NTH  512
#define NCOL 64    // h-columns owned per CTA (per gate), cluster of 2

// Shared memory layout (float offsets)
#define FS   33    // feature-major row stride (odd -> conflict-free column reads)
#define AS   68    // aggT dup-pair row stride (68*4=272 B, 16B-aligned rows)

#define SMO_H0   0                          // [2][128*FS] double buffered
#define SMO_H1   (SMO_H0 + 2*H_*FS)         // 8448
#define SMO_C0   (SMO_H1 + 2*H_*FS)         // 16896  [32][NCOL] local cols
#define SMO_C1   (SMO_C0 + N_*NCOL)         // 18944
#define SMO_AGG  (SMO_C1 + N_*NCOL)         // 20992  [256][AS] dup-pair layout
#define SMO_X    (SMO_AGG + F1_*AS)         // 38400  [32][FS]
#define SMO_AN   (SMO_X + D_*FS)            // 39456  [m][n] 32x32
#define SMO_DINV (SMO_AN + N_*N_)           // 40480
#define SMO_RED  (SMO_DINV + 32)            // 40512  k-split partials: 4096 u64
#define SM_FLOATS (SMO_RED + 2*4096)        // 48704
#define SM_BYTES (SM_FLOATS * 4)            // 194816 B

// Output buffer offsets: (output, zlat, mu, logvar, output_logvar)
#define OFF_OUT 0
#define OFF_Z   (B_*T_*N_*D_)
#define OFF_MU  (OFF_Z  + B_*N_*H_)
#define OFF_LV  (OFF_MU + B_*N_*H_)
#define OFF_OLV (OFF_LV + B_*N_*H_)

// ---------------- packed f32x2 helpers ----------------
__device__ __forceinline__ ull pk2(float lo, float hi) {
    ull r;
    asm("mov.b64 %0, {%1, %2};" : "=l"(r) : "f"(lo), "f"(hi));
    return r;
}
__device__ __forceinline__ void upk2(ull v, float& lo, float& hi) {
    asm("mov.b64 {%0, %1}, %2;" : "=f"(lo), "=f"(hi) : "l"(v));
}
__device__ __forceinline__ ull ffma2(ull a, ull b, ull c) {
    ull d;
    asm("fma.rn.f32x2 %0, %1, %2, %3;" : "=l"(d) : "l"(a), "l"(b), "l"(c));
    return d;
}
__device__ __forceinline__ ull fadd2(ull a, ull b) {
    ull d;
    asm("add.rn.f32x2 %0, %1, %2;" : "=l"(d) : "l"(a), "l"(b));
    return d;
}

// ---------------- cluster helpers ----------------
__device__ __forceinline__ uint32_t smem_u32(const void* p) {
    uint32_t a;
    asm("{ .reg .u64 t; cvta.to.shared.u64 t, %1; cvt.u32.u64 %0, t; }"
        : "=r"(a) : "l"(p));
    return a;
}
__device__ __forceinline__ uint32_t map_peer(uint32_t laddr, uint32_t peer_rank) {
    uint32_t r;
    asm("mapa.shared::cluster.u32 %0, %1, %2;" : "=r"(r) : "r"(laddr), "r"(peer_rank));
    return r;
}
__device__ __forceinline__ void stc_f32(uint32_t addr, float v) {
    asm volatile("st.shared::cluster.f32 [%0], %1;" :: "r"(addr), "f"(v) : "memory");
}
#define CSYNC() do { \
    asm volatile("barrier.cluster.arrive.aligned;" ::: "memory"); \
    asm volatile("barrier.cluster.wait.aligned;"   ::: "memory"); \
} while (0)

// ---------------- activations (accurate: exp-based) ----------------
__device__ __forceinline__ float sigf(float x) {
    return __fdividef(1.0f, 1.0f + __expf(-x));
}
__device__ __forceinline__ float tanhg(float x) {
    return __fdividef(2.0f, 1.0f + __expf(-2.0f * x)) - 1.0f;
}

// ---------------- GCN aggregation (n-split across thread pairs) --------------
// aggT[f][2n]=aggT[f][2n+1]= sum_m An[n][m]*src[f][m]; An stored transposed [m][n].
// thread = (f, hh): hh owns n-range [hh*16, hh*16+16).
template<int F, int R0>
__device__ __forceinline__ void agg_f(float* __restrict__ aggT,
                                      const float* __restrict__ An,
                                      const float* __restrict__ s0,
                                      const float* __restrict__ s1,
                                      int tid) {
    const int f  = tid >> 1;
    const int hh = tid & 1;
    if (f < F) {
        const float* src = (f < R0) ? (s0 + f * FS) : (s1 + (f - R0) * FS);
        const float* Anh = An + hh * 16;
        ull acc[8];
        #pragma unroll
        for (int p = 0; p < 8; p++) acc[p] = 0ULL;
        #pragma unroll 4
        for (int m = 0; m < 32; m++) {
            const float xv = src[m];
            const ull xd = pk2(xv, xv);
            const ulonglong2 w0 = *(const ulonglong2*)(Anh + m * 32);      // n hh*16..+7
            const ulonglong2 w1 = *(const ulonglong2*)(Anh + m * 32 + 8);  // n hh*16+8..+15
            acc[0] = ffma2(xd, w0.x, acc[0]);
            acc[1] = ffma2(xd, w0.y, acc[1]);
            acc[2] = ffma2(xd, w1.x, acc[2]);
            acc[3] = ffma2(xd, w1.y, acc[3]);
        }
        // second 8 n's share the same LDS stream: fold into one pass
        // (acc[4..7] accumulated below with the second half of each 16-float row)
        // NOTE: w0/w1 above already cover 8 floats = 8 n's... need 16 n's:
        // redo with 4 loads per m handled in the loop above is cheaper; see store.
        // -- acc[4..7] computed in a second m-pass to keep register pressure low:
        #pragma unroll 4
        for (int m = 0; m < 32; m++) {
            const float xv = src[m];
            const ull xd = pk2(xv, xv);
            const ulonglong2 w2 = *(const ulonglong2*)(Anh + m * 32 + 4);
            const ulonglong2 w3 = *(const ulonglong2*)(Anh + m * 32 + 12);
            acc[4] = ffma2(xd, w2.x, acc[4]);
            acc[5] = ffma2(xd, w2.y, acc[5]);
            acc[6] = ffma2(xd, w3.x, acc[6]);
            acc[7] = ffma2(xd, w3.y, acc[7]);
        }
        float* dst = aggT + f * AS + hh * 32;
        // n order: acc0,1 -> n+0..3 ; acc4,5 -> n+4..7 ; acc2,3 -> n+8..11 ; acc6,7 -> n+12..15
        {
            float a, b;
            upk2(acc[0], a, b); *(float4*)(dst + 0)  = make_float4(a, a, b, b);
            upk2(acc[1], a, b); *(float4*)(dst + 4)  = make_float4(a, a, b, b);
            upk2(acc[4], a, b); *(float4*)(dst + 8)  = make_float4(a, a, b, b);
            upk2(acc[5], a, b); *(float4*)(dst + 12) = make_float4(a, a, b, b);
            upk2(acc[2], a, b); *(float4*)(dst + 16) = make_float4(a, a, b, b);
            upk2(acc[3], a, b); *(float4*)(dst + 20) = make_float4(a, a, b, b);
            upk2(acc[6], a, b); *(float4*)(dst + 24) = make_float4(a, a, b, b);
            upk2(acc[7], a, b); *(float4*)(dst + 28) = make_float4(a, a, b, b);
        }
    }
}

// ---------------- LSTM cell half: K-split GEMM + gates -----------------------
// 512 threads: half = tid>>8 owns K-range [half*K/2, (half+1)*K/2).
// Logical tile per (t2 = tid&255): rows n0=rg*4..+3, col pair jl=cg*2, all 4 gates.
template<int K>
__device__ __forceinline__ void gemm_gates(const float* __restrict__ W,
                                           const float* __restrict__ bias,
                                           const float* __restrict__ aggT,
                                           float* __restrict__ hT,
                                           uint32_t hT_peer,
                                           float* __restrict__ cB,
                                           ull* __restrict__ redS,
                                           int rank, int tid) {
    const int half = tid >> 8;
    const int t2   = tid & 255;
    const int rg = t2 >> 5;
    const int cg = t2 & 31;
    const int n0 = rg * 4;
    const int jl = cg * 2;
    const int jg = rank * NCOL + jl;

    ull acc[4][4];                     // [row r][gate g]
    if (half == 0) {
        #pragma unroll
        for (int g = 0; g < 4; g++) {
            const ull bv = *(const ull*)(bias + g * H_ + jg);
            acc[0][g] = bv; acc[1][g] = bv; acc[2][g] = bv; acc[3][g] = bv;
        }
    } else {
        #pragma unroll
        for (int g = 0; g < 4; g++) {
            acc[0][g] = 0ULL; acc[1][g] = 0ULL; acc[2][g] = 0ULL; acc[3][g] = 0ULL;
        }
    }

    const int k0 = half * (K / 2);
    const float* ap = aggT + k0 * AS + n0 * 2;  // dup-pair layout
    const float* wp = W + k0 * G4_ + jg;
    #pragma unroll 2
    for (int k = 0; k < K / 2; k++) {
        const ulonglong2 a01 = *(const ulonglong2*)ap;        // (a0,a0),(a1,a1)
        const ulonglong2 a23 = *(const ulonglong2*)(ap + 4);  // (a2,a2),(a3,a3)
        ap += AS;
        #pragma unroll
        for (int g = 0; g < 4; g++) {
            const ull w = __ldg((const ull*)(wp + g * H_));
            acc[0][g] = ffma2(a01.x, w, acc[0][g]);
            acc[1][g] = ffma2(a01.y, w, acc[1][g]);
            acc[2][g] = ffma2(a23.x, w, acc[2][g]);
            acc[3][g] = ffma2(a23.y, w, acc[3][g]);
        }
        wp += G4_;
    }

    if (half == 1) {
        #pragma unroll
        for (int r = 0; r < 4; r++)
            #pragma unroll
            for (int g = 0; g < 4; g++)
                redS[(r * 4 + g) * 256 + t2] = acc[r][g];
    }
    __syncthreads();

    if (half == 0) {
        #pragma unroll
        for (int r = 0; r < 4; r++)
            #pragma unroll
            for (int g = 0; g < 4; g++)
                acc[r][g] = fadd2(acc[r][g], redS[(r * 4 + g) * 256 + t2]);

        #pragma unroll
        for (int r = 0; r < 4; r++) {
            const int n = n0 + r;
            float i0, i1, f0, f1, g0, g1, o0, o1;
            upk2(acc[r][0], i0, i1);
            upk2(acc[r][1], f0, f1);
            upk2(acc[r][2], g0, g1);
            upk2(acc[r][3], o0, o1);
            float2 c = *(float2*)(cB + n * NCOL + jl);
            const float cn0 = sigf(f0) * c.x + sigf(i0) * tanhg(g0);
            const float cn1 = sigf(f1) * c.y + sigf(i1) * tanhg(g1);
            *(float2*)(cB + n * NCOL + jl) = make_float2(cn0, cn1);
            const float hv0 = sigf(o0) * tanhg(cn0);
            const float hv1 = sigf(o1) * tanhg(cn1);
            const int o0i = jg * FS + n;
            const int o1i = o0i + FS;
            hT[o0i] = hv0;
            hT[o1i] = hv1;
            stc_f32(hT_peer + o0i * 4, hv0);   // exchange h chunk to peer CTA
            stc_f32(hT_peer + o1i * 4, hv1);
        }
    }
}

// ---------------- latent head (runs once; split cols by rank) ----------------
__device__ __forceinline__ void pnl_H(const float* __restrict__ h1T,
                                      const float* __restrict__ Wmu, const float* __restrict__ bmu,
                                      const float* __restrict__ Wlv, const float* __restrict__ blv,
                                      const float* __restrict__ eps_g,
                                      float* __restrict__ gmu, float* __restrict__ glv,
                                      float* __restrict__ gz,
                                      float* __restrict__ zbuf, uint32_t zbuf_peer,
                                      int b, int rank, int tid) {
    if (tid >= 256) return;
    const int n  = tid >> 3;
    const int j0 = rank * NCOL + (tid & 7) * 8;
    float am[8] = {0,0,0,0,0,0,0,0};
    float al[8] = {0,0,0,0,0,0,0,0};
    const float* wm = Wmu + n * (H_ * H_) + j0;
    const float* wl = Wlv + n * (H_ * H_) + j0;
    const float* hp = h1T + n;
    for (int h = 0; h < H_; h++) {
        const float a = hp[h * FS];
        const float4 u0 = __ldg((const float4*)wm);
        const float4 u1 = __ldg((const float4*)(wm + 4));
        const float4 v0 = __ldg((const float4*)wl);
        const float4 v1 = __ldg((const float4*)(wl + 4));
        am[0] = fmaf(a, u0.x, am[0]); am[1] = fmaf(a, u0.y, am[1]);
        am[2] = fmaf(a, u0.z, am[2]); am[3] = fmaf(a, u0.w, am[3]);
        am[4] = fmaf(a, u1.x, am[4]); am[5] = fmaf(a, u1.y, am[5]);
        am[6] = fmaf(a, u1.z, am[6]); am[7] = fmaf(a, u1.w, am[7]);
        al[0] = fmaf(a, v0.x, al[0]); al[1] = fmaf(a, v0.y, al[1]);
        al[2] = fmaf(a, v0.z, al[2]); al[3] = fmaf(a, v0.w, al[3]);
        al[4] = fmaf(a, v1.x, al[4]); al[5] = fmaf(a, v1.y, al[5]);
        al[6] = fmaf(a, v1.z, al[6]); al[7] = fmaf(a, v1.w, al[7]);
        wm += H_; wl += H_;
    }
    const int gbase = b * (N_ * H_) + n * H_ + j0;
    const int bbase = n * H_ + j0;
    #pragma unroll
    for (int c = 0; c < 8; c++) {
        const float m = am[c] + bmu[bbase + c];
        const float l = al[c] + blv[bbase + c];
        const float z = m + eps_g[gbase + c] * __expf(l);
        gmu[gbase + c] = m;
        glv[gbase + c] = l;
        gz[gbase + c]  = z;
        const int zi = (j0 + c) * AS + n;   // feature-major staged z (stride AS)
        zbuf[zi] = z;
        stc_f32(zbuf_peer + zi * 4, z);
    }
}

// ---------------- output head (split d-cols by rank; also feeds back xT) ------
__device__ __forceinline__ void pnl_D(const float* __restrict__ srcT, int sstride,
                                      const float* __restrict__ Who, const float* __restrict__ bho,
                                      const float* __restrict__ Wholv, const float* __restrict__ bholv,
                                      float* __restrict__ gout, float* __restrict__ goutlv,
                                      float* __restrict__ xT, uint32_t xT_peer,
                                      int b, int tt, int rank, int tid) {
    if (tid >= 256) return;
    const int n  = tid >> 3;
    const int d0 = rank * 16 + (tid & 7) * 2;
    ull ao = 0ULL, av = 0ULL;
    const float* w1 = Who   + n * (H_ * D_) + d0;
    const float* w2 = Wholv + n * (H_ * D_) + d0;
    const float* sp = srcT + n;
    #pragma unroll 4
    for (int h = 0; h < H_; h++) {
        const float a = sp[h * sstride];
        const ull ad = pk2(a, a);
        ao = ffma2(ad, __ldg((const ull*)w1), ao);
        av = ffma2(ad, __ldg((const ull*)w2), av);
        w1 += D_; w2 += D_;
    }
    float o0, o1, q0, q1;
    upk2(ao, o0, o1);
    upk2(av, q0, q1);
    const int bb = n * D_ + d0;
    o0 += bho[bb];   o1 += bho[bb + 1];
    q0 += bholv[bb]; q1 += bholv[bb + 1];
    const int goff = (b * T_ + tt) * (N_ * D_) + n * D_ + d0;
    *(float2*)(gout + goff)   = make_float2(o0, o1);
    *(float2*)(goutlv + goff) = make_float2(q0, q1);
    const int x0 = d0 * FS + n;
    xT[x0]      = o0;
    xT[x0 + FS] = o1;
    stc_f32(xT_peer + x0 * 4,        o0);
    stc_f32(xT_peer + (x0 + FS) * 4, o1);
}

// ---------------- main: cluster of 2 CTAs per batch element ----------------
__global__ void __launch_bounds__(NTH, 1) __cluster_dims__(2, 1, 1)
glstm_kernel(const float* __restrict__ ts, const int* __restrict__ ei,
             const float* __restrict__ Wen0, const float* __restrict__ ben0,
             const float* __restrict__ Wen1, const float* __restrict__ ben1,
             const float* __restrict__ Wde0, const float* __restrict__ bde0,
             const float* __restrict__ Wde1, const float* __restrict__ bde1,
             const float* __restrict__ Wmu, const float* __restrict__ bmu,
             const float* __restrict__ Wlv, const float* __restrict__ blv,
             const float* __restrict__ Who, const float* __restrict__ bho,
             const float* __restrict__ Wholv, const float* __restrict__ bholv,
             const float* __restrict__ eps, float* __restrict__ out) {
    extern __shared__ float sm[];
    const int tid = threadIdx.x;
    const int b   = blockIdx.x >> 1;
    uint32_t rank;
    asm("mov.u32 %0, %%cluster_ctarank;" : "=r"(rank));
    const uint32_t lbase = smem_u32(sm);
    const uint32_t pbase = map_peer(lbase, rank ^ 1u);

    float* h0buf = sm + SMO_H0;
    float* h1buf = sm + SMO_H1;
    float* c0B   = sm + SMO_C0;
    float* c1B   = sm + SMO_C1;
    float* aggT  = sm + SMO_AGG;
    float* xT    = sm + SMO_X;
    float* An    = sm + SMO_AN;
    float* dinv  = sm + SMO_DINV;
    ull*   redS  = (ull*)(sm + SMO_RED);

    float* gout   = out + OFF_OUT;
    float* gz     = out + OFF_Z;
    float* gmu    = out + OFF_MU;
    float* glv    = out + OFF_LV;
    float* goutlv = out + OFF_OLV;

    // ---- init: zero state, build normalized adjacency (duplicated per CTA) ----
    for (int i = tid; i < SMO_AGG; i += NTH) sm[i] = 0.0f;   // h0/h1 (both bufs), c0, c1
    float* C = aggT;                                          // scratch counts [n][m]
    for (int i = tid; i < N_ * N_; i += NTH) C[i] = 0.0f;
    __syncthreads();
    if (tid < E_) atomicAdd(&C[ei[E_ + tid] * N_ + ei[tid]], 1.0f);
    __syncthreads();
    if (tid < N_) {
        C[tid * N_ + tid] += 1.0f;
        float s = 0.0f;
        for (int m = 0; m < N_; m++) s += C[tid * N_ + m];
        dinv[tid] = 1.0f / sqrtf(s);
    }
    __syncthreads();
    for (int i = tid; i < N_ * N_; i += NTH) {
        const int n = i >> 5, m = i & 31;
        An[m * N_ + n] = dinv[n] * C[i] * dinv[m];            // store transposed [m][n]
    }
    CSYNC();   // peer init complete before any remote h writes

    // ---- encoder (steps 0..T-1) ----
    for (int s = 0; s < T_; s++) {
        const int p = s & 1;
        float* h0c = h0buf + p * (H_ * FS);
        float* h0p = h0buf + (p ^ 1) * (H_ * FS);
        float* h1c = h1buf + p * (H_ * FS);
        float* h1p = h1buf + (p ^ 1) * (H_ * FS);
        {   // stage x_t feature-major (full, per CTA)
            const int n = tid >> 4, d0 = (tid & 15) * 2;
            const float2 v = *(const float2*)(ts + ((b * T_ + s) * N_ + n) * D_ + d0);
            xT[(d0 + 0) * FS + n] = v.x;
            xT[(d0 + 1) * FS + n] = v.y;
        }
        __syncthreads();
        agg_f<F0_, D_>(aggT, An, xT, h0p, tid);
        __syncthreads();
        gemm_gates<F0_>(Wen0, ben0, aggT, h0c,
                        pbase + (uint32_t)(SMO_H0 + p * H_ * FS) * 4, c0B, redS, rank, tid);
        CSYNC();
        agg_f<F1_, H_>(aggT, An, h0c, h1p, tid);
        __syncthreads();
        gemm_gates<F1_>(Wen1, ben1, aggT, h1c,
                        pbase + (uint32_t)(SMO_H1 + p * H_ * FS) * 4, c1B, redS, rank, tid);
        CSYNC();
    }

    // ---- latent head ----
    float* h1f = h1buf + ((T_ - 1) & 1) * (H_ * FS);
    pnl_H(h1f, Wmu, bmu, Wlv, blv, eps, gmu, glv, gz,
          aggT, pbase + (uint32_t)SMO_AGG * 4, b, (int)rank, tid);
    CSYNC();
    pnl_D(aggT, AS, Who, bho, Wholv, bholv, gout, goutlv,
          xT, pbase + (uint32_t)SMO_X * 4, b, T_ - 1, (int)rank, tid);
    CSYNC();

    // ---- decoder (steps T..2T-2 -> timesteps T-2..0) ----
    for (int s = T_; s < 2 * T_ - 1; s++) {
        const int p = s & 1;
        float* h0c = h0buf + p * (H_ * FS);
        float* h0p = h0buf + (p ^ 1) * (H_ * FS);
        float* h1c = h1buf + p * (H_ * FS);
        float* h1p = h1buf + (p ^ 1) * (H_ * FS);
        agg_f<F0_, D_>(aggT, An, xT, h0p, tid);
        __syncthreads();
        gemm_gates<F0_>(Wde0, bde0, aggT, h0c,
                        pbase + (uint32_t)(SMO_H0 + p * H_ * FS) * 4, c0B, redS, rank, tid);
        CSYNC();
        agg_f<F1_, H_>(aggT, An, h0c, h1p, tid);
        __syncthreads();
        gemm_gates<F1_>(Wde1, bde1, aggT, h1c,
                        pbase + (uint32_t)(SMO_H1 + p * H_ * FS) * 4, c1B, redS, rank, tid);
        CSYNC();
        pnl_D(h1c, FS, Who, bho, Wholv, bholv, gout, goutlv,
              xT, pbase + (uint32_t)SMO_X * 4, b, T_ - 2 - (s - T_), (int)rank, tid);
        CSYNC();
    }
}

extern "C" void kernel_launch(void* const* d_in, const int* in_sizes, int n_in,
                              void* d_out, int out_size) {
    (void)in_sizes; (void)n_in; (void)out_size;
    const float* ts    = (const float*)d_in[0];
    const int*   ei    = (const int*)  d_in[1];
    const float* Wen0  = (const float*)d_in[2];
    const float* ben0  = (const float*)d_in[3];
    const float* Wen1  = (const float*)d_in[4];
    const float* ben1  = (const float*)d_in[5];
    const float* Wde0  = (const float*)d_in[6];
    const float* bde0  = (const float*)d_in[7];
    const float* Wde1  = (const float*)d_in[8];
    const float* bde1  = (const float*)d_in[9];
    const float* Wmu   = (const float*)d_in[10];
    const float* bmu   = (const float*)d_in[11];
    const float* Wlv   = (const float*)d_in[12];
    const float* blv   = (const float*)d_in[13];
    const float* Who   = (const float*)d_in[14];
    const float* bho   = (const float*)d_in[15];
    const float* Wholv = (const float*)d_in[16];
    const float* bholv = (const float*)d_in[17];
    const float* eps   = (const float*)d_in[18];
    float* o = (float*)d_out;

    cudaFuncSetAttribute(glstm_kernel, cudaFuncAttributeMaxDynamicSharedMemorySize, SM_BYTES);
    glstm_kernel<<<B_ * 2, NTH, SM_BYTES>>>(ts, ei, Wen0, ben0, Wen1, ben1,
                                            Wde0, bde0, Wde1, bde1,
                                            Wmu, bmu, Wlv, blv,
                                            Who, bho, Wholv, bholv, eps, o);
}